// round 11
// baseline (speedup 1.0000x reference)
#include <cuda_runtime.h>
#include <cstdint>

typedef unsigned long long u64;

#define B_  16
#define N_  8192
#define C_  256
#define K_  4096

// Output layout (float32): [features][indices][adjacency][scores]
#define OFF_FEAT   ((size_t)0)
#define OFF_IDX    ((size_t)B_ * K_ * C_)
#define OFF_ADJ    (OFF_IDX + (size_t)B_ * K_)
#define OFF_SCORES (OFF_ADJ + (size_t)B_ * K_ * K_)

// Scratch (device globals; no allocation allowed)
__device__ __align__(16) unsigned short g_idx[B_ * K_];
__device__ int g_pos[B_ * N_];
__device__ __align__(16) u64 g_keys[B_ * N_];      // 1 MB sort scratch

// ---------------------------------------------------------------------------
// Bitonic convention (chunk-local): at stage (k, j), the lower element of a
// pair keeps the max iff (local_i & k)==0  => EVERY chunk independently
// sorted descending (required by the merge-path ranker).  Composite key
// flipped_score<<16 | (8191-idx) breaks ties by ascending index
// (jax.lax.top_k) and makes all keys unique => strict total order.
// ---------------------------------------------------------------------------
__device__ __forceinline__ void ce_pair(u64 &lo, u64 &hi, bool desc) {
    u64 a = lo, b = hi;
    u64 mx = a > b ? a : b;
    u64 mn = a > b ? b : a;
    lo = desc ? mx : mn;
    hi = desc ? mn : mx;
}
__device__ __forceinline__ u64 shfl_ce(u64 v, int j, bool keepmax) {
    u64 o = __shfl_xor_sync(0xFFFFFFFFu, v, j);
    u64 mx = v > o ? v : o;
    u64 mn = v > o ? o : v;
    return keepmax ? mx : mn;
}
__device__ __forceinline__ void smem_ce(u64* s, int i, int m, bool desc) {
    u64 a = s[i], c = s[m];
    if ((a < c) == desc) { s[i] = c; s[m] = a; }
}

// ---------------------------------------------------------------------------
// K1: sort each 2048-chunk fully DESCENDING (k=2..2048, chunk-local desc).
// grid B*4, block 512, 4 u64/thread, 16KB smem. Builds keys, clears g_pos.
// ---------------------------------------------------------------------------
__global__ __launch_bounds__(512)
void sort2048_kernel(const float* __restrict__ scores)
{
    __shared__ u64 s[2048];
    const int b  = blockIdx.x >> 2;
    const int cb = (blockIdx.x & 3) << 11;          // batch-local chunk base
    const int t  = threadIdx.x;
    const int l  = t & 31;
    const int wbase = (t >> 5) << 7;                // warp*128 (chunk-local)
    const float* sc = scores + (size_t)b * N_;

    u64 v[4];
    #pragma unroll
    for (int e = 0; e < 4; e++) {
        int I = cb + wbase + e * 32 + l;            // batch-local (for key)
        unsigned u = __float_as_uint(sc[I]);
        u ^= (u & 0x80000000u) ? 0xFFFFFFFFu : 0x80000000u;
        v[e] = ((u64)u << 16) | (unsigned)(8191 - I);
        g_pos[b * N_ + cb + e * 512 + t] = -1;
    }

    // ---- register phase: k = 2..128 (chunk-local indices only) ----
    #pragma unroll
    for (int k = 2; k <= 128; k <<= 1) {
        #pragma unroll
        for (int eb = 2; eb >= 1; eb >>= 1) {
            const int j = eb << 5;
            if (j < k) {
                #pragma unroll
                for (int e = 0; e < 4; e++)
                    if (!(e & eb)) {
                        bool desc = (((wbase + e * 32) & k) == 0);
                        ce_pair(v[e], v[e | eb], desc);
                    }
            }
        }
        #pragma unroll
        for (int j = 16; j >= 1; j >>= 1) {
            if (j < k) {
                #pragma unroll
                for (int e = 0; e < 4; e++) {
                    bool desc = (((wbase + e * 32 + l) & k) == 0);
                    v[e] = shfl_ce(v[e], j, desc == ((l & j) == 0));
                }
            }
        }
    }

    // ---- k = 256..2048: smem stages j>=128, register tail j<=64 ----
    #pragma unroll 1
    for (int k = 256; k <= 2048; k <<= 1) {
        #pragma unroll
        for (int e = 0; e < 4; e++) s[wbase + e * 32 + l] = v[e];
        __syncthreads();
        #pragma unroll 1
        for (int j = k >> 1; j >= 128; j >>= 1) {
            #pragma unroll
            for (int q = 0; q < 2; q++) {
                int p = t + q * 512;                       // 0..1023
                int i = ((p & ~(j - 1)) << 1) | (p & (j - 1));
                bool desc = ((i & k) == 0);                // chunk-local
                smem_ce(s, i, i + j, desc);
            }
            __syncthreads();
        }
        #pragma unroll
        for (int e = 0; e < 4; e++) v[e] = s[wbase + e * 32 + l];
        __syncthreads();
        #pragma unroll
        for (int eb = 2; eb >= 1; eb >>= 1) {
            #pragma unroll
            for (int e = 0; e < 4; e++)
                if (!(e & eb)) {
                    bool desc = (((wbase + e * 32) & k) == 0);
                    ce_pair(v[e], v[e | eb], desc);
                }
        }
        #pragma unroll
        for (int j = 16; j >= 1; j >>= 1) {
            #pragma unroll
            for (int e = 0; e < 4; e++) {
                bool desc = (((wbase + e * 32 + l) & k) == 0);
                v[e] = shfl_ce(v[e], j, desc == ((l & j) == 0));
            }
        }
    }

    #pragma unroll
    for (int e = 0; e < 4; e++)
        g_keys[(size_t)b * N_ + cb + wbase + e * 32 + l] = v[e];
}

// ---------------------------------------------------------------------------
// K2: merge-path rank + emit (unchanged, proven).
// ---------------------------------------------------------------------------
__global__ __launch_bounds__(512)
void rank_emit_kernel(float* __restrict__ out_idxf,
                      float* __restrict__ out_scores)
{
    const int gid = blockIdx.x * 512 + threadIdx.x;    // 0 .. B*N-1
    const int b = gid >> 13;
    const int i = gid & (N_ - 1);
    const u64* keys = g_keys + (size_t)b * N_;
    const u64 x = keys[i];
    const int chunk = i >> 11;
    int rank = i & 2047;                               // greater elems in own chunk

    #pragma unroll
    for (int c = 0; c < 4; c++) {
        if (c == chunk) continue;
        const u64* a = keys + (c << 11);
        int lo = 0, hi = 2048;
        while (lo < hi) {                              // <= 12 iterations
            int mid = (lo + hi) >> 1;
            if (a[mid] > x) lo = mid + 1; else hi = mid;
        }
        rank += lo;                                    // # elements > x in chunk c
    }

    if (rank < K_) {
        int idx = 8191 - (int)(x & 0xFFFF);
        unsigned ku = (unsigned)(x >> 16);
        unsigned orig = (ku & 0x80000000u) ? (ku ^ 0x80000000u) : ~ku;
        g_idx[b * K_ + rank] = (unsigned short)idx;
        out_idxf[(size_t)b * K_ + rank]   = (float)idx;
        out_scores[(size_t)b * K_ + rank] = __uint_as_float(orig);
        g_pos[b * N_ + idx] = rank;
    }
}

// ---------------------------------------------------------------------------
// Combined gather.  Adjacency branch: prefetch ALL 16 g_pos lookups with full
// MLP before the sync (removes a ~16 x 234cyc serialized L2 dependency chain
// from the batch loop), stage the source row in SMEM, then serve each
// selected batch with explicitly unrolled idx4-load / store pairs.
// ---------------------------------------------------------------------------
__global__ __launch_bounds__(512)
void gather_kernel(const float* __restrict__ A,
                   const float4* __restrict__ feat,
                   float* __restrict__ out_adj,
                   float4* __restrict__ out_feat)
{
    __shared__ float row[N_];   // 32 KB (adj branch only)
    if (blockIdx.x < 8192) {
        const int r = blockIdx.x;

        // prefetch pos map entries for this row, all 16 in flight
        int pos[B_];
        #pragma unroll
        for (int b = 0; b < B_; ++b)
            pos[b] = g_pos[b * N_ + r];

        const float4* src  = (const float4*)(A + (size_t)r * N_);
        float4*       rowv = (float4*)row;
        for (int t = threadIdx.x; t < N_ / 4; t += 512)
            rowv[t] = __ldcs(src + t);
        __syncthreads();

        #pragma unroll 1
        for (int b = 0; b < B_; ++b) {
            int i = pos[b];
            if (i < 0) continue;
            float4* obase = (float4*)(out_adj + ((size_t)b * K_ + i) * K_);
            const ushort4* idx4 = (const ushort4*)(g_idx + b * K_);
            // K_/4 = 1024 elements, 512 threads => exactly 2 iterations:
            // issue both index loads first (MLP), then both stores.
            ushort4 c0 = idx4[threadIdx.x];
            ushort4 c1 = idx4[threadIdx.x + 512];
            __stcs(obase + threadIdx.x,
                   make_float4(row[c0.x], row[c0.y], row[c0.z], row[c0.w]));
            __stcs(obase + threadIdx.x + 512,
                   make_float4(row[c1.x], row[c1.y], row[c1.z], row[c1.w]));
        }
    } else {
        int o = (blockIdx.x - 8192) * 512 + threadIdx.x;   // 0..4194303
        int frow = o >> 6;                                  // C/4=64 f4/row
        int c    = o & 63;
        int b    = frow >> 12;                              // K rows/batch
        int r    = g_idx[frow];
        __stcs(out_feat + o,
               __ldcs(feat + ((size_t)(b << 13) + r) * 64 + c));
    }
}

// ---------------------------------------------------------------------------
extern "C" void kernel_launch(void* const* d_in, const int* in_sizes, int n_in,
                              void* d_out, int out_size)
{
    const float* scores = (const float*)d_in[0];   // (B, N)
    const float* feat   = (const float*)d_in[1];   // (B, N, C)
    const float* adj    = (const float*)d_in[2];   // (N, N)
    float* out = (float*)d_out;

    float* out_feat   = out + OFF_FEAT;
    float* out_idxf   = out + OFF_IDX;
    float* out_adj    = out + OFF_ADJ;
    float* out_scores = out + OFF_SCORES;

    sort2048_kernel<<<B_ * 4, 512>>>(scores);
    rank_emit_kernel<<<B_ * N_ / 512, 512>>>(out_idxf, out_scores);

    gather_kernel<<<16384, 512>>>(adj, (const float4*)feat,
                                  out_adj, (float4*)out_feat);
}

// round 12
// speedup vs baseline: 1.0743x; 1.0743x over previous
#include <cuda_runtime.h>
#include <cstdint>

typedef unsigned long long u64;

#define B_  16
#define N_  8192
#define C_  256
#define K_  4096

// Output layout (float32): [features][indices][adjacency][scores]
#define OFF_FEAT   ((size_t)0)
#define OFF_IDX    ((size_t)B_ * K_ * C_)
#define OFF_ADJ    (OFF_IDX + (size_t)B_ * K_)
#define OFF_SCORES (OFF_ADJ + (size_t)B_ * K_ * K_)

// Scratch (device globals; no allocation allowed)
__device__ __align__(16) unsigned short g_idx[B_ * K_];
__device__ int g_pos[B_ * N_];
__device__ __align__(16) u64 g_keys[B_ * N_];      // 1 MB sort scratch

// ---------------------------------------------------------------------------
// Bitonic convention (chunk-local): at stage (k, j), the lower element of a
// pair keeps the max iff (local_i & k)==0  => EVERY chunk independently
// sorted descending (required by the merge-path ranker).  Composite key
// flipped_score<<16 | (8191-idx) breaks ties by ascending index
// (jax.lax.top_k) and makes all keys unique => strict total order.
// ---------------------------------------------------------------------------
__device__ __forceinline__ void ce_pair(u64 &lo, u64 &hi, bool desc) {
    u64 a = lo, b = hi;
    u64 mx = a > b ? a : b;
    u64 mn = a > b ? b : a;
    lo = desc ? mx : mn;
    hi = desc ? mn : mx;
}
__device__ __forceinline__ u64 shfl_ce(u64 v, int j, bool keepmax) {
    u64 o = __shfl_xor_sync(0xFFFFFFFFu, v, j);
    u64 mx = v > o ? v : o;
    u64 mn = v > o ? o : v;
    return keepmax ? mx : mn;
}
__device__ __forceinline__ void smem_ce(u64* s, int i, int m, bool desc) {
    u64 a = s[i], c = s[m];
    if ((a < c) == desc) { s[i] = c; s[m] = a; }
}

// ---------------------------------------------------------------------------
// K1: sort each 1024-chunk fully DESCENDING (k=2..1024, chunk-local desc).
// grid B*8 = 128, block 256, 4 u64/thread, 8KB smem.  Shorter serial chain
// than 2048-chunks (6 smem sweeps vs 10).  Builds keys, clears g_pos.
// ---------------------------------------------------------------------------
__global__ __launch_bounds__(256)
void sort1024_kernel(const float* __restrict__ scores)
{
    __shared__ u64 s[1024];
    const int b  = blockIdx.x >> 3;
    const int cb = (blockIdx.x & 7) << 10;          // batch-local chunk base
    const int t  = threadIdx.x;
    const int l  = t & 31;
    const int wbase = (t >> 5) << 7;                // warp*128 (chunk-local)
    const float* sc = scores + (size_t)b * N_;

    u64 v[4];
    #pragma unroll
    for (int e = 0; e < 4; e++) {
        int I = cb + wbase + e * 32 + l;            // batch-local (for key)
        unsigned u = __float_as_uint(sc[I]);
        u ^= (u & 0x80000000u) ? 0xFFFFFFFFu : 0x80000000u;
        v[e] = ((u64)u << 16) | (unsigned)(8191 - I);
        g_pos[b * N_ + cb + e * 256 + t] = -1;
    }

    // ---- register phase: k = 2..128 (chunk-local indices only) ----
    #pragma unroll
    for (int k = 2; k <= 128; k <<= 1) {
        #pragma unroll
        for (int eb = 2; eb >= 1; eb >>= 1) {
            const int j = eb << 5;
            if (j < k) {
                #pragma unroll
                for (int e = 0; e < 4; e++)
                    if (!(e & eb)) {
                        bool desc = (((wbase + e * 32) & k) == 0);
                        ce_pair(v[e], v[e | eb], desc);
                    }
            }
        }
        #pragma unroll
        for (int j = 16; j >= 1; j >>= 1) {
            if (j < k) {
                #pragma unroll
                for (int e = 0; e < 4; e++) {
                    bool desc = (((wbase + e * 32 + l) & k) == 0);
                    v[e] = shfl_ce(v[e], j, desc == ((l & j) == 0));
                }
            }
        }
    }

    // ---- k = 256, 512, 1024: smem stages j>=128, register tail j<=64 ----
    #pragma unroll 1
    for (int k = 256; k <= 1024; k <<= 1) {
        #pragma unroll
        for (int e = 0; e < 4; e++) s[wbase + e * 32 + l] = v[e];
        __syncthreads();
        #pragma unroll 1
        for (int j = k >> 1; j >= 128; j >>= 1) {
            #pragma unroll
            for (int q = 0; q < 2; q++) {
                int p = t + q * 256;                       // 0..511 pairs
                int i = ((p & ~(j - 1)) << 1) | (p & (j - 1));
                bool desc = ((i & k) == 0);                // chunk-local
                smem_ce(s, i, i + j, desc);
            }
            __syncthreads();
        }
        #pragma unroll
        for (int e = 0; e < 4; e++) v[e] = s[wbase + e * 32 + l];
        __syncthreads();
        #pragma unroll
        for (int eb = 2; eb >= 1; eb >>= 1) {
            #pragma unroll
            for (int e = 0; e < 4; e++)
                if (!(e & eb)) {
                    bool desc = (((wbase + e * 32) & k) == 0);
                    ce_pair(v[e], v[e | eb], desc);
                }
        }
        #pragma unroll
        for (int j = 16; j >= 1; j >>= 1) {
            #pragma unroll
            for (int e = 0; e < 4; e++) {
                bool desc = (((wbase + e * 32 + l) & k) == 0);
                v[e] = shfl_ce(v[e], j, desc == ((l & j) == 0));
            }
        }
    }

    #pragma unroll
    for (int e = 0; e < 4; e++)
        g_keys[(size_t)b * N_ + cb + wbase + e * 32 + l] = v[e];
}

// ---------------------------------------------------------------------------
// K2: merge-path rank + emit over 8 descending 1024-chunks.  Global rank =
// position-in-own-chunk + sum over the other 7 chunks of count(> x) via
// binary search (unique keys => exact; searches independent => 7-way MLP).
// Invariant: a[0..lo) > x, a[hi..1024) <= x; terminates in <= 11 iterations.
// ---------------------------------------------------------------------------
__global__ __launch_bounds__(512)
void rank_emit_kernel(float* __restrict__ out_idxf,
                      float* __restrict__ out_scores)
{
    const int gid = blockIdx.x * 512 + threadIdx.x;    // 0 .. B*N-1
    const int b = gid >> 13;
    const int i = gid & (N_ - 1);
    const u64* keys = g_keys + (size_t)b * N_;
    const u64 x = keys[i];
    const int chunk = i >> 10;
    int rank = i & 1023;                               // greater elems in own chunk

    #pragma unroll
    for (int c = 0; c < 8; c++) {
        if (c == chunk) continue;
        const u64* a = keys + (c << 10);
        int lo = 0, hi = 1024;
        while (lo < hi) {                              // <= 11 iterations
            int mid = (lo + hi) >> 1;
            if (a[mid] > x) lo = mid + 1; else hi = mid;
        }
        rank += lo;                                    // # elements > x in chunk c
    }

    if (rank < K_) {
        int idx = 8191 - (int)(x & 0xFFFF);
        unsigned ku = (unsigned)(x >> 16);
        unsigned orig = (ku & 0x80000000u) ? (ku ^ 0x80000000u) : ~ku;
        g_idx[b * K_ + rank] = (unsigned short)idx;
        out_idxf[(size_t)b * K_ + rank]   = (float)idx;
        out_scores[(size_t)b * K_ + rank] = __uint_as_float(orig);
        g_pos[b * N_ + idx] = rank;
    }
}

// ---------------------------------------------------------------------------
// Combined gather — round-10 proven form, byte-for-byte.  Blocks [0,8192)
// stage one adjacency source row in SMEM and serve every batch containing
// it; blocks [8192,16384) gather features.  Streaming hints keep L2 for
// the hot g_idx.
// ---------------------------------------------------------------------------
__global__ __launch_bounds__(512)
void gather_kernel(const float* __restrict__ A,
                   const float4* __restrict__ feat,
                   float* __restrict__ out_adj,
                   float4* __restrict__ out_feat)
{
    __shared__ float row[N_];   // 32 KB (adj branch only)
    if (blockIdx.x < 8192) {
        const int r = blockIdx.x;
        const float4* src  = (const float4*)(A + (size_t)r * N_);
        float4*       rowv = (float4*)row;
        for (int t = threadIdx.x; t < N_ / 4; t += 512)
            rowv[t] = __ldcs(src + t);
        __syncthreads();

        #pragma unroll 1
        for (int b = 0; b < B_; ++b) {
            int i = g_pos[b * N_ + r];
            if (i < 0) continue;
            float4* obase = (float4*)(out_adj + ((size_t)b * K_ + i) * K_);
            const ushort4* idx4 = (const ushort4*)(g_idx + b * K_);
            for (int t = threadIdx.x; t < K_ / 4; t += 512) {
                ushort4 c = idx4[t];
                __stcs(obase + t,
                       make_float4(row[c.x], row[c.y], row[c.z], row[c.w]));
            }
        }
    } else {
        int o = (blockIdx.x - 8192) * 512 + threadIdx.x;   // 0..4194303
        int frow = o >> 6;                                  // C/4=64 f4/row
        int c    = o & 63;
        int b    = frow >> 12;                              // K rows/batch
        int r    = g_idx[frow];
        __stcs(out_feat + o,
               __ldcs(feat + ((size_t)(b << 13) + r) * 64 + c));
    }
}

// ---------------------------------------------------------------------------
extern "C" void kernel_launch(void* const* d_in, const int* in_sizes, int n_in,
                              void* d_out, int out_size)
{
    const float* scores = (const float*)d_in[0];   // (B, N)
    const float* feat   = (const float*)d_in[1];   // (B, N, C)
    const float* adj    = (const float*)d_in[2];   // (N, N)
    float* out = (float*)d_out;

    float* out_feat   = out + OFF_FEAT;
    float* out_idxf   = out + OFF_IDX;
    float* out_adj    = out + OFF_ADJ;
    float* out_scores = out + OFF_SCORES;

    sort1024_kernel<<<B_ * 8, 256>>>(scores);
    rank_emit_kernel<<<B_ * N_ / 512, 512>>>(out_idxf, out_scores);

    gather_kernel<<<16384, 512>>>(adj, (const float4*)feat,
                                  out_adj, (float4*)out_feat);
}